// round 1
// baseline (speedup 1.0000x reference)
#include <cuda_runtime.h>

// ---------------- problem constants ----------------
#define Hh   128
#define Bb   16
#define Nn   1000
#define SFf  20
#define Ee   20000              // edges per graph = Nn*SFf
#define NODE_ROWS (Bb*Nn)       // 16000
#define EDGE_ROWS (Bb*Ee)       // 320000
#define BN_EPS 1e-5f

#define BM 64                   // GEMM rows per block
#define GEMM_SMEM (128*128*4 + 128*(BM+4)*4)   // W tile + transposed A tile = 100352 B
#define STATS_BLOCKS 256

// ---------------- scratch (__device__ globals; no allocation allowed) ----------------
__device__ float g_Ux [NODE_ROWS*Hh];   // Ux, then reused as x_tmp
__device__ float g_Vx [NODE_ROWS*Hh];
__device__ float g_Vxf[NODE_ROWS*Hh];
__device__ float g_Vxt[NODE_ROWS*Hh];
__device__ float g_e1 [EDGE_ROWS*Hh];   // Ve_lin, then reused as e_tmp
__device__ float g_e2 [EDGE_ROWS*Hh];   // Ue
__device__ float g_e3 [EDGE_ROWS*Hh];   // iUe
__device__ float g_psum[STATS_BLOCKS*Hh];
__device__ float g_psq [STATS_BLOCKS*Hh];
__device__ float g_mean[Hh];
__device__ float g_rstd[Hh];

// ---------------- GEMM: out[r][c] = sum_k A[r][k]*W[k][c] + bias[c] ----------------
// Full K=128 resident in smem. 256 threads, 64 rows/block, 4x8 register tile/thread.
__global__ __launch_bounds__(256)
void gemm_kernel(const float* __restrict__ A, const float* __restrict__ W,
                 const float* __restrict__ bias, float* __restrict__ out, int R)
{
    extern __shared__ float sm[];
    float* Ws = sm;                      // [128][128] row-major (k-major)
    float* As = sm + 128*128;            // [128][BM+4] transposed: As[k][r]
    const int tid  = threadIdx.x;
    const int row0 = blockIdx.x * BM;

    // load full W (4096 float4), coalesced
    {
        const float4* Wg  = (const float4*)W;
        float4*       Ws4 = (float4*)Ws;
        #pragma unroll
        for (int i = 0; i < 16; ++i) Ws4[i*256 + tid] = Wg[i*256 + tid];
    }
    // load A tile (64 rows x 128), store transposed
    {
        #pragma unroll
        for (int i = 0; i < 8; ++i) {
            int idx = i*256 + tid;       // 0..2047
            int r   = idx >> 5;          // 0..63
            int kq  = idx & 31;          // float4 index within row
            int grow = row0 + r;
            float4 v = make_float4(0.f,0.f,0.f,0.f);
            if (grow < R) v = ((const float4*)A)[(size_t)grow*32 + kq];
            int k = kq*4;
            As[(k+0)*(BM+4) + r] = v.x;
            As[(k+1)*(BM+4) + r] = v.y;
            As[(k+2)*(BM+4) + r] = v.z;
            As[(k+3)*(BM+4) + r] = v.w;
        }
    }
    __syncthreads();

    const int rg = tid >> 4;             // 0..15 -> rows rg*4..rg*4+3
    const int cg = tid & 15;             // 0..15 -> cols cg*8..cg*8+7

    float acc[4][8];
    #pragma unroll
    for (int i = 0; i < 4; ++i)
        #pragma unroll
        for (int j = 0; j < 8; ++j) acc[i][j] = 0.f;

    #pragma unroll 4
    for (int k = 0; k < 128; ++k) {
        float4 av = *(const float4*)&As[k*(BM+4) + rg*4];
        float4 b0 = *(const float4*)&Ws[k*128 + cg*8];
        float4 b1 = *(const float4*)&Ws[k*128 + cg*8 + 4];
        float a[4] = {av.x, av.y, av.z, av.w};
        float b[8] = {b0.x, b0.y, b0.z, b0.w, b1.x, b1.y, b1.z, b1.w};
        #pragma unroll
        for (int i = 0; i < 4; ++i)
            #pragma unroll
            for (int j = 0; j < 8; ++j) acc[i][j] += a[i] * b[j];
    }

    float bs[8];
    #pragma unroll
    for (int j = 0; j < 8; ++j) bs[j] = bias[cg*8 + j];

    #pragma unroll
    for (int i = 0; i < 4; ++i) {
        int grow = row0 + rg*4 + i;
        if (grow < R) {
            float4 o0 = make_float4(acc[i][0]+bs[0], acc[i][1]+bs[1],
                                    acc[i][2]+bs[2], acc[i][3]+bs[3]);
            float4 o1 = make_float4(acc[i][4]+bs[4], acc[i][5]+bs[5],
                                    acc[i][6]+bs[6], acc[i][7]+bs[7]);
            ((float4*)out)[(size_t)grow*32 + cg*2    ] = o0;
            ((float4*)out)[(size_t)grow*32 + cg*2 + 1] = o1;
        }
    }
}

// ---------------- softmax over SF + gather-aggregate + Ux add ----------------
// block = (b,n); thread = channel h. x_tmp[b,n,h] = Ux + sum_s softmax_s(Ve)[s]*Vx[gather]
__global__ __launch_bounds__(Hh)
void softmax_agg_kernel(const float* __restrict__ Ve, const float* __restrict__ Vx,
                        const float* __restrict__ Ux_in, const int* __restrict__ edge_index,
                        float* __restrict__ xtmp)
{
    int bn = blockIdx.x;
    int b = bn / Nn, n = bn % Nn;
    int h = threadIdx.x;
    __shared__ int sidx[SFf];
    if (h < SFf) sidx[h] = edge_index[(size_t)b*Ee + n*SFf + h];
    __syncthreads();

    const float* vep = Ve + ((size_t)b*Ee + (size_t)n*SFf)*Hh + h;
    float v[SFf];
    float m = -1e30f;
    #pragma unroll
    for (int s = 0; s < SFf; ++s) { v[s] = vep[s*Hh]; m = fmaxf(m, v[s]); }
    float den = 0.f;
    #pragma unroll
    for (int s = 0; s < SFf; ++s) { v[s] = expf(v[s] - m); den += v[s]; }
    float agg = 0.f;
    #pragma unroll
    for (int s = 0; s < SFf; ++s)
        agg += v[s] * Vx[((size_t)b*Nn + sidx[s])*Hh + h];

    size_t o = (size_t)bn*Hh + h;
    xtmp[o] = Ux_in[o] + agg / den;     // Ux_in may alias xtmp (read-before-write per thread)
}

// ---------------- BN stats: stage 1 (deterministic partials) ----------------
__global__ __launch_bounds__(Hh)
void rowstats_kernel(const float* __restrict__ t, int R)
{
    int h = threadIdx.x;
    float s = 0.f, q = 0.f;
    for (int r = blockIdx.x; r < R; r += gridDim.x) {
        float v = t[(size_t)r*Hh + h];
        s += v; q += v*v;
    }
    g_psum[blockIdx.x*Hh + h] = s;
    g_psq [blockIdx.x*Hh + h] = q;
}

// ---------------- BN stats: stage 2 (finalize mean / rstd) ----------------
__global__ __launch_bounds__(Hh)
void finalize_stats_kernel(float inv_count)
{
    int h = threadIdx.x;
    float s = 0.f, q = 0.f;
    #pragma unroll 8
    for (int i = 0; i < STATS_BLOCKS; ++i) { s += g_psum[i*Hh + h]; q += g_psq[i*Hh + h]; }
    float mean = s * inv_count;
    float var  = q * inv_count - mean*mean;   // biased, matches jnp.var
    g_mean[h] = mean;
    g_rstd[h] = rsqrtf(var + BN_EPS);
}

// ---------------- apply BN + ReLU + residual ----------------
__global__ __launch_bounds__(256)
void bn_apply_kernel(const float* __restrict__ resid, const float* __restrict__ tmp,
                     const float* __restrict__ gamma, const float* __restrict__ beta,
                     float* __restrict__ out, int R)
{
    size_t total = (size_t)R * Hh;
    for (size_t idx = (size_t)blockIdx.x*blockDim.x + threadIdx.x; idx < total;
         idx += (size_t)gridDim.x*blockDim.x) {
        int h = (int)(idx & (Hh-1));
        float v = (tmp[idx] - g_mean[h]) * g_rstd[h] * gamma[h] + beta[h];
        out[idx] = resid[idx] + fmaxf(v, 0.f);
    }
}

// ---------------- e_tmp = Ue + Vxt[gather] + Vxf[bcast] + inv_emb ----------------
__global__ __launch_bounds__(Hh)
void etmp_kernel(const float* __restrict__ Ue,  const float* __restrict__ iUe,
                 const float* __restrict__ Vxf, const float* __restrict__ Vxt,
                 const float* __restrict__ Wph, const int* __restrict__ edge_index,
                 const int* __restrict__ inv_index, float* __restrict__ etmp)
{
    int bn = blockIdx.x;
    int b = bn / Nn, n = bn % Nn;
    int h = threadIdx.x;
    __shared__ int sidx[SFf], sinv[SFf];
    if (h < SFf) {
        sidx[h] = edge_index[(size_t)b*Ee + n*SFf + h];
        sinv[h] = inv_index [(size_t)b*Ee + n*SFf + h];
    }
    __syncthreads();

    float vf  = Vxf[((size_t)b*Nn + n)*Hh + h];
    float wph = Wph[h];
    #pragma unroll
    for (int s = 0; s < SFf; ++s) {
        size_t eo = ((size_t)b*Ee + (size_t)n*SFf + s)*Hh + h;
        int inv = sinv[s];
        float ie = (inv < Ee) ? iUe[((size_t)b*Ee + inv)*Hh + h] : wph;
        etmp[eo] = Ue[eo] + Vxt[((size_t)b*Nn + sidx[s])*Hh + h] + vf + ie;
    }
}

// ---------------- launch ----------------
extern "C" void kernel_launch(void* const* d_in, const int* in_sizes, int n_in,
                              void* d_out, int out_size)
{
    const float* x        = (const float*)d_in[0];
    const float* e        = (const float*)d_in[1];
    const int*   eidx     = (const int*)  d_in[2];
    const int*   inv_idx  = (const int*)  d_in[3];
    const float* node_w   = (const float*)d_in[4];
    const float* node_b   = (const float*)d_in[5];
    const float* to_w     = (const float*)d_in[6];
    const float* to_b     = (const float*)d_in[7];
    const float* ee_w     = (const float*)d_in[8];
    const float* ee_b     = (const float*)d_in[9];
    const float* U_w      = (const float*)d_in[10];
    const float* U_b      = (const float*)d_in[11];
    const float* Vf_w     = (const float*)d_in[12];
    const float* Vf_b     = (const float*)d_in[13];
    const float* Vt_w     = (const float*)d_in[14];
    const float* Vt_b     = (const float*)d_in[15];
    const float* iU_w     = (const float*)d_in[16];
    const float* iU_b     = (const float*)d_in[17];
    const float* W_ph     = (const float*)d_in[18];
    const float* bnn_g    = (const float*)d_in[19];
    const float* bnn_b    = (const float*)d_in[20];
    const float* bne_g    = (const float*)d_in[21];
    const float* bne_b    = (const float*)d_in[22];

    float* out  = (float*)d_out;
    float* xnew = out;                       // [B,N,H]
    float* enew = out + (size_t)NODE_ROWS*Hh; // [B,E,H]

    float *pUx, *pVx, *pVxf, *pVxt, *pe1, *pe2, *pe3;
    cudaGetSymbolAddress((void**)&pUx,  g_Ux);
    cudaGetSymbolAddress((void**)&pVx,  g_Vx);
    cudaGetSymbolAddress((void**)&pVxf, g_Vxf);
    cudaGetSymbolAddress((void**)&pVxt, g_Vxt);
    cudaGetSymbolAddress((void**)&pe1,  g_e1);
    cudaGetSymbolAddress((void**)&pe2,  g_e2);
    cudaGetSymbolAddress((void**)&pe3,  g_e3);

    cudaFuncSetAttribute(gemm_kernel, cudaFuncAttributeMaxDynamicSharedMemorySize, GEMM_SMEM);

    const int nodeBlocks = NODE_ROWS / BM;   // 250
    const int edgeBlocks = EDGE_ROWS / BM;   // 5000

    // ---- NodeFeatures ----
    gemm_kernel<<<nodeBlocks, 256, GEMM_SMEM>>>(x, node_w, node_b, pUx, NODE_ROWS);
    gemm_kernel<<<nodeBlocks, 256, GEMM_SMEM>>>(x, to_w,   to_b,   pVx, NODE_ROWS);
    gemm_kernel<<<edgeBlocks, 256, GEMM_SMEM>>>(e, ee_w,   ee_b,   pe1, EDGE_ROWS);
    softmax_agg_kernel<<<Bb*Nn, Hh>>>(pe1, pVx, pUx, eidx, pUx);      // g_Ux becomes x_tmp
    rowstats_kernel<<<STATS_BLOCKS, Hh>>>(pUx, NODE_ROWS);
    finalize_stats_kernel<<<1, Hh>>>(1.0f / (float)NODE_ROWS);
    bn_apply_kernel<<<1024, 256>>>(x, pUx, bnn_g, bnn_b, xnew, NODE_ROWS);

    // ---- EdgeFeatures ----
    gemm_kernel<<<edgeBlocks, 256, GEMM_SMEM>>>(e,    U_w,  U_b,  pe2,  EDGE_ROWS);
    gemm_kernel<<<edgeBlocks, 256, GEMM_SMEM>>>(e,    iU_w, iU_b, pe3,  EDGE_ROWS);
    gemm_kernel<<<nodeBlocks, 256, GEMM_SMEM>>>(xnew, Vf_w, Vf_b, pVxf, NODE_ROWS);
    gemm_kernel<<<nodeBlocks, 256, GEMM_SMEM>>>(xnew, Vt_w, Vt_b, pVxt, NODE_ROWS);
    etmp_kernel<<<Bb*Nn, Hh>>>(pe2, pe3, pVxf, pVxt, W_ph, eidx, inv_idx, pe1); // g_e1 = e_tmp
    rowstats_kernel<<<STATS_BLOCKS, Hh>>>(pe1, EDGE_ROWS);
    finalize_stats_kernel<<<1, Hh>>>(1.0f / (float)EDGE_ROWS);
    bn_apply_kernel<<<2048, 256>>>(e, pe1, bne_g, bne_b, enew, EDGE_ROWS);
}

// round 3
// speedup vs baseline: 1.7674x; 1.7674x over previous
#include <cuda_runtime.h>
#include <cuda_bf16.h>
#include <cstdint>

// ---------------- problem constants ----------------
#define Hh   128
#define Bb   16
#define Nn   1000
#define SFf  20
#define Ee   20000
#define NODE_ROWS (Bb*Nn)        // 16000  = 125*128
#define EDGE_ROWS (Bb*Ee)        // 320000 = 2500*128
#define BN_EPS 1e-5f
#define STATS_BLOCKS 256

// smem tile: 4 buffers of 128 x 136 bf16 (row padded by 8 for conflict-free ldmatrix)
#define TPAD 136
#define TBUF (128*TPAD)
#define SM_TOT (4*TBUF*2)        // 139264 bytes

// ---------------- scratch (__device__ globals) ----------------
__device__ float g_Ux [NODE_ROWS*Hh];
__device__ float g_Vx [NODE_ROWS*Hh];
__device__ float g_Vxf[NODE_ROWS*Hh];
__device__ float g_Vxt[NODE_ROWS*Hh];
__device__ float g_e1 [(size_t)EDGE_ROWS*Hh];
__device__ float g_e2 [(size_t)EDGE_ROWS*Hh];
__device__ float g_e3 [(size_t)EDGE_ROWS*Hh];
__device__ float g_psum[STATS_BLOCKS*Hh];
__device__ float g_psq [STATS_BLOCKS*Hh];
__device__ float g_mean[Hh];
__device__ float g_rstd[Hh];

__device__ __nv_bfloat16 g_ehi [(size_t)EDGE_ROWS*Hh];
__device__ __nv_bfloat16 g_elo [(size_t)EDGE_ROWS*Hh];
__device__ __nv_bfloat16 g_xhi [NODE_ROWS*Hh];
__device__ __nv_bfloat16 g_xlo [NODE_ROWS*Hh];
__device__ __nv_bfloat16 g_xnhi[NODE_ROWS*Hh];
__device__ __nv_bfloat16 g_xnlo[NODE_ROWS*Hh];
__device__ __nv_bfloat16 g_wthi[7][128*128];   // transposed [n][k] hi
__device__ __nv_bfloat16 g_wtlo[7][128*128];   // transposed [n][k] lo

// ---------------- helpers ----------------
__device__ __forceinline__ uint32_t smem_u32(const void* p) {
    uint32_t a;
    asm("{ .reg .u64 t; cvta.to.shared.u64 t, %1; cvt.u32.u64 %0, t; }" : "=r"(a) : "l"(p));
    return a;
}
__device__ __forceinline__ void ldsm_x4(uint32_t* r, uint32_t addr) {
    asm volatile("ldmatrix.sync.aligned.m8n8.x4.shared.b16 {%0,%1,%2,%3}, [%4];"
                 : "=r"(r[0]), "=r"(r[1]), "=r"(r[2]), "=r"(r[3]) : "r"(addr));
}
__device__ __forceinline__ void mma_bf16(float* c, const uint32_t* a, const uint32_t* b) {
    asm volatile("mma.sync.aligned.m16n8k16.row.col.f32.bf16.bf16.f32 "
                 "{%0,%1,%2,%3}, {%4,%5,%6,%7}, {%8,%9}, {%0,%1,%2,%3};"
                 : "+f"(c[0]), "+f"(c[1]), "+f"(c[2]), "+f"(c[3])
                 : "r"(a[0]), "r"(a[1]), "r"(a[2]), "r"(a[3]), "r"(b[0]), "r"(b[1]));
}

// ---------------- tensor-core GEMM ----------------
// out[tile of 128 rows][128] = (Ahi+Alo)[tile][128] @ W^T + bias
// W stored transposed [n][k] (k contiguous) = col-major B for mma .row.col.
// Split precision: D = Ah*Wh + Al*Wh + Ah*Wl (fp32 accum; dropped Al*Wl ~2^-18).
__global__ __launch_bounds__(256)
void mma_gemm_kernel(const __nv_bfloat16* __restrict__ Ah, const __nv_bfloat16* __restrict__ Al,
                     const __nv_bfloat16* __restrict__ Bh, const __nv_bfloat16* __restrict__ Bl,
                     const float* __restrict__ bias, float* __restrict__ out)
{
    extern __shared__ __nv_bfloat16 sm[];
    __nv_bfloat16* Ash = sm;
    __nv_bfloat16* Als = sm + TBUF;
    __nv_bfloat16* Bhs = sm + 2*TBUF;
    __nv_bfloat16* Bls = sm + 3*TBUF;

    const int tid  = threadIdx.x;
    const size_t row0 = (size_t)blockIdx.x * 128;

    // ---- load tiles: 128 rows x 128 bf16 = 2048 uint4 per buffer ----
    {
        const uint4* gA  = (const uint4*)(Ah + row0*128);
        const uint4* gAl = (const uint4*)(Al + row0*128);
        const uint4* gB  = (const uint4*)Bh;
        const uint4* gBl = (const uint4*)Bl;
        #pragma unroll
        for (int i = 0; i < 8; ++i) {
            int idx = i*256 + tid;           // 0..2047
            int r = idx >> 4, c = idx & 15;  // row, 8-elem chunk
            int o = r*TPAD + c*8;
            *(uint4*)(Ash + o) = gA[idx];
            *(uint4*)(Als + o) = gAl[idx];
            *(uint4*)(Bhs + o) = gB[idx];
            *(uint4*)(Bls + o) = gBl[idx];
        }
    }
    __syncthreads();

    const int warp = tid >> 5, lane = tid & 31;
    const int wr = warp & 3;       // row group: rows wr*32 .. +32
    const int wc = warp >> 2;      // col group: cols wc*64 .. +64

    float acc[2][8][4];
    #pragma unroll
    for (int mt = 0; mt < 2; ++mt)
        #pragma unroll
        for (int nt = 0; nt < 8; ++nt)
            #pragma unroll
            for (int i = 0; i < 4; ++i) acc[mt][nt][i] = 0.f;

    const uint32_t a_hi = smem_u32(Ash), a_lo = smem_u32(Als);
    const uint32_t b_hi = smem_u32(Bhs), b_lo = smem_u32(Bls);

    // per-thread ldmatrix element offsets (in elements, *2 for bytes)
    // A m-tile: row = wr*32 + mt*16 + (lane&15), k = k0 + (lane>>4)*8
    const int a_row = wr*32 + (lane & 15);
    const int a_koff = (lane >> 4) * 8;
    // B n-tile pair: n = wc*64 + p*16 + (lane&7) + ((lane>>4)&1)*8, k = k0 + ((lane>>3)&1)*8
    const int b_n   = wc*64 + (lane & 7) + ((lane >> 4) & 1)*8;
    const int b_koff = ((lane >> 3) & 1) * 8;

    #pragma unroll
    for (int ks = 0; ks < 8; ++ks) {
        const int k0 = ks * 16;
        uint32_t ah[2][4], al[2][4];
        #pragma unroll
        for (int mt = 0; mt < 2; ++mt) {
            uint32_t off = (uint32_t)((a_row + mt*16)*TPAD + k0 + a_koff) * 2u;
            ldsm_x4(ah[mt], a_hi + off);
            ldsm_x4(al[mt], a_lo + off);
        }
        #pragma unroll
        for (int p = 0; p < 4; ++p) {
            uint32_t bh[4], bl[4];
            uint32_t off = (uint32_t)((b_n + p*16)*TPAD + k0 + b_koff) * 2u;
            ldsm_x4(bh, b_hi + off);
            ldsm_x4(bl, b_lo + off);
            #pragma unroll
            for (int mt = 0; mt < 2; ++mt) {
                mma_bf16(acc[mt][2*p  ], ah[mt], bh);
                mma_bf16(acc[mt][2*p  ], al[mt], bh);
                mma_bf16(acc[mt][2*p  ], ah[mt], bl);
                mma_bf16(acc[mt][2*p+1], ah[mt], bh + 2);
                mma_bf16(acc[mt][2*p+1], al[mt], bh + 2);
                mma_bf16(acc[mt][2*p+1], ah[mt], bl + 2);
            }
        }
    }

    // ---- epilogue: D frag (m=gid,n=2tg),(m=gid,n=2tg+1),(m=gid+8,..) ----
    const int gid = lane >> 2, tg = lane & 3;
    #pragma unroll
    for (int mt = 0; mt < 2; ++mt) {
        #pragma unroll
        for (int nt = 0; nt < 8; ++nt) {
            int col = wc*64 + nt*8 + tg*2;
            float b0 = bias[col], b1 = bias[col+1];
            size_t r0 = row0 + wr*32 + mt*16 + gid;
            float2 v0 = make_float2(acc[mt][nt][0] + b0, acc[mt][nt][1] + b1);
            float2 v1 = make_float2(acc[mt][nt][2] + b0, acc[mt][nt][3] + b1);
            *(float2*)(out + r0*128 + col)       = v0;
            *(float2*)(out + (r0+8)*128 + col)   = v1;
        }
    }
}

// ---------------- fp32 -> bf16 hi/lo split ----------------
__global__ __launch_bounds__(256)
void split_kernel(const float* __restrict__ in, __nv_bfloat16* __restrict__ hi,
                  __nv_bfloat16* __restrict__ lo, int n8)
{
    int stride = gridDim.x * blockDim.x;
    for (int i = blockIdx.x*blockDim.x + threadIdx.x; i < n8; i += stride) {
        float4 a = ((const float4*)in)[2*i];
        float4 b = ((const float4*)in)[2*i + 1];
        float v[8] = {a.x, a.y, a.z, a.w, b.x, b.y, b.z, b.w};
        __align__(16) __nv_bfloat16 h[8], l[8];
        #pragma unroll
        for (int j = 0; j < 8; ++j) {
            h[j] = __float2bfloat16(v[j]);
            l[j] = __float2bfloat16(v[j] - __bfloat162float(h[j]));
        }
        *(uint4*)(hi + (size_t)i*8) = *(const uint4*)h;
        *(uint4*)(lo + (size_t)i*8) = *(const uint4*)l;
    }
}

// ---------------- weight transpose + split ----------------
__global__ __launch_bounds__(128)
void wsplit_kernel(const float* __restrict__ W, __nv_bfloat16* __restrict__ hi,
                   __nv_bfloat16* __restrict__ lo)
{
    int k = blockIdx.x, c = threadIdx.x;
    float v = W[k*128 + c];
    __nv_bfloat16 h = __float2bfloat16(v);
    hi[c*128 + k] = h;
    lo[c*128 + k] = __float2bfloat16(v - __bfloat162float(h));
}

// ---------------- softmax over SF + gather-aggregate + Ux add ----------------
__global__ __launch_bounds__(Hh)
void softmax_agg_kernel(const float* __restrict__ Ve, const float* __restrict__ Vx,
                        const float* __restrict__ Ux_in, const int* __restrict__ edge_index,
                        float* __restrict__ xtmp)
{
    int bn = blockIdx.x;
    int b = bn / Nn, n = bn % Nn;
    int h = threadIdx.x;
    __shared__ int sidx[SFf];
    if (h < SFf) sidx[h] = edge_index[(size_t)b*Ee + n*SFf + h];
    __syncthreads();

    const float* vep = Ve + ((size_t)b*Ee + (size_t)n*SFf)*Hh + h;
    float v[SFf];
    float m = -1e30f;
    #pragma unroll
    for (int s = 0; s < SFf; ++s) { v[s] = vep[s*Hh]; m = fmaxf(m, v[s]); }
    float den = 0.f;
    #pragma unroll
    for (int s = 0; s < SFf; ++s) { v[s] = expf(v[s] - m); den += v[s]; }
    float agg = 0.f;
    #pragma unroll
    for (int s = 0; s < SFf; ++s)
        agg += v[s] * Vx[((size_t)b*Nn + sidx[s])*Hh + h];

    size_t o = (size_t)bn*Hh + h;
    xtmp[o] = Ux_in[o] + agg / den;
}

// ---------------- BN stats stage 1 ----------------
__global__ __launch_bounds__(Hh)
void rowstats_kernel(const float* __restrict__ t, int R)
{
    int h = threadIdx.x;
    float s = 0.f, q = 0.f;
    for (int r = blockIdx.x; r < R; r += gridDim.x) {
        float v = t[(size_t)r*Hh + h];
        s += v; q += v*v;
    }
    g_psum[blockIdx.x*Hh + h] = s;
    g_psq [blockIdx.x*Hh + h] = q;
}

// ---------------- BN stats stage 2 ----------------
__global__ __launch_bounds__(Hh)
void finalize_stats_kernel(float inv_count)
{
    int h = threadIdx.x;
    float s = 0.f, q = 0.f;
    #pragma unroll 8
    for (int i = 0; i < STATS_BLOCKS; ++i) { s += g_psum[i*Hh + h]; q += g_psq[i*Hh + h]; }
    float mean = s * inv_count;
    float var  = q * inv_count - mean*mean;
    g_mean[h] = mean;
    g_rstd[h] = rsqrtf(var + BN_EPS);
}

// ---------------- BN apply + ReLU + residual ----------------
__global__ __launch_bounds__(256)
void bn_apply_kernel(const float* __restrict__ resid, const float* __restrict__ tmp,
                     const float* __restrict__ gamma, const float* __restrict__ beta,
                     float* __restrict__ out, int R)
{
    size_t total = (size_t)R * Hh;
    for (size_t idx = (size_t)blockIdx.x*blockDim.x + threadIdx.x; idx < total;
         idx += (size_t)gridDim.x*blockDim.x) {
        int h = (int)(idx & (Hh-1));
        float v = (tmp[idx] - g_mean[h]) * g_rstd[h] * gamma[h] + beta[h];
        out[idx] = resid[idx] + fmaxf(v, 0.f);
    }
}

// ---------------- e_tmp = Ue + Vxt[gather] + Vxf + inv_emb ----------------
__global__ __launch_bounds__(Hh)
void etmp_kernel(const float* __restrict__ Ue,  const float* __restrict__ iUe,
                 const float* __restrict__ Vxf, const float* __restrict__ Vxt,
                 const float* __restrict__ Wph, const int* __restrict__ edge_index,
                 const int* __restrict__ inv_index, float* __restrict__ etmp)
{
    int bn = blockIdx.x;
    int b = bn / Nn, n = bn % Nn;
    int h = threadIdx.x;
    __shared__ int sidx[SFf], sinv[SFf];
    if (h < SFf) {
        sidx[h] = edge_index[(size_t)b*Ee + n*SFf + h];
        sinv[h] = inv_index [(size_t)b*Ee + n*SFf + h];
    }
    __syncthreads();

    float vf  = Vxf[((size_t)b*Nn + n)*Hh + h];
    float wph = Wph[h];
    #pragma unroll
    for (int s = 0; s < SFf; ++s) {
        size_t eo = ((size_t)b*Ee + (size_t)n*SFf + s)*Hh + h;
        int inv = sinv[s];
        float ie = (inv < Ee) ? iUe[((size_t)b*Ee + inv)*Hh + h] : wph;
        etmp[eo] = Ue[eo] + Vxt[((size_t)b*Nn + sidx[s])*Hh + h] + vf + ie;
    }
}

// ---------------- launch ----------------
extern "C" void kernel_launch(void* const* d_in, const int* in_sizes, int n_in,
                              void* d_out, int out_size)
{
    const float* x       = (const float*)d_in[0];
    const float* e       = (const float*)d_in[1];
    const int*   eidx    = (const int*)  d_in[2];
    const int*   inv_idx = (const int*)  d_in[3];
    const float* node_w  = (const float*)d_in[4];
    const float* node_b  = (const float*)d_in[5];
    const float* to_w    = (const float*)d_in[6];
    const float* to_b    = (const float*)d_in[7];
    const float* ee_w    = (const float*)d_in[8];
    const float* ee_b    = (const float*)d_in[9];
    const float* U_w     = (const float*)d_in[10];
    const float* U_b     = (const float*)d_in[11];
    const float* Vf_w    = (const float*)d_in[12];
    const float* Vf_b    = (const float*)d_in[13];
    const float* Vt_w    = (const float*)d_in[14];
    const float* Vt_b    = (const float*)d_in[15];
    const float* iU_w    = (const float*)d_in[16];
    const float* iU_b    = (const float*)d_in[17];
    const float* W_ph    = (const float*)d_in[18];
    const float* bnn_g   = (const float*)d_in[19];
    const float* bnn_b   = (const float*)d_in[20];
    const float* bne_g   = (const float*)d_in[21];
    const float* bne_b   = (const float*)d_in[22];

    float* out  = (float*)d_out;
    float* xnew = out;
    float* enew = out + (size_t)NODE_ROWS*Hh;

    float *pUx, *pVx, *pVxf, *pVxt, *pe1, *pe2, *pe3;
    cudaGetSymbolAddress((void**)&pUx,  g_Ux);
    cudaGetSymbolAddress((void**)&pVx,  g_Vx);
    cudaGetSymbolAddress((void**)&pVxf, g_Vxf);
    cudaGetSymbolAddress((void**)&pVxt, g_Vxt);
    cudaGetSymbolAddress((void**)&pe1,  g_e1);
    cudaGetSymbolAddress((void**)&pe2,  g_e2);
    cudaGetSymbolAddress((void**)&pe3,  g_e3);

    __nv_bfloat16 *pehi, *pelo, *pxhi, *pxlo, *pxnhi, *pxnlo, *pwh, *pwl;
    cudaGetSymbolAddress((void**)&pehi,  g_ehi);
    cudaGetSymbolAddress((void**)&pelo,  g_elo);
    cudaGetSymbolAddress((void**)&pxhi,  g_xhi);
    cudaGetSymbolAddress((void**)&pxlo,  g_xlo);
    cudaGetSymbolAddress((void**)&pxnhi, g_xnhi);
    cudaGetSymbolAddress((void**)&pxnlo, g_xnlo);
    cudaGetSymbolAddress((void**)&pwh,   g_wthi);
    cudaGetSymbolAddress((void**)&pwl,   g_wtlo);

    cudaFuncSetAttribute(mma_gemm_kernel, cudaFuncAttributeMaxDynamicSharedMemorySize, SM_TOT);

    const int nodeBlocks = NODE_ROWS / 128;   // 125
    const int edgeBlocks = EDGE_ROWS / 128;   // 2500

    // weight transpose+split: order = node,to,ee,U,iU,Vf,Vt
    const float* Ws[7] = {node_w, to_w, ee_w, U_w, iU_w, Vf_w, Vt_w};
    for (int i = 0; i < 7; ++i)
        wsplit_kernel<<<128, 128>>>(Ws[i], pwh + (size_t)i*128*128, pwl + (size_t)i*128*128);

    split_kernel<<<256, 256>>>(x, pxhi, pxlo, NODE_ROWS*Hh/8);
    split_kernel<<<2048, 256>>>(e, pehi, pelo, EDGE_ROWS/8*Hh);

    // ---- NodeFeatures ----
    mma_gemm_kernel<<<nodeBlocks, 256, SM_TOT>>>(pxhi, pxlo, pwh + 0*16384, pwl + 0*16384, node_b, pUx);
    mma_gemm_kernel<<<nodeBlocks, 256, SM_TOT>>>(pxhi, pxlo, pwh + 1*16384, pwl + 1*16384, to_b,   pVx);
    mma_gemm_kernel<<<edgeBlocks, 256, SM_TOT>>>(pehi, pelo, pwh + 2*16384, pwl + 2*16384, ee_b,   pe1);
    softmax_agg_kernel<<<Bb*Nn, Hh>>>(pe1, pVx, pUx, eidx, pUx);
    rowstats_kernel<<<STATS_BLOCKS, Hh>>>(pUx, NODE_ROWS);
    finalize_stats_kernel<<<1, Hh>>>(1.0f / (float)NODE_ROWS);
    bn_apply_kernel<<<1024, 256>>>(x, pUx, bnn_g, bnn_b, xnew, NODE_ROWS);

    // ---- EdgeFeatures ----
    split_kernel<<<256, 256>>>(xnew, pxnhi, pxnlo, NODE_ROWS*Hh/8);
    mma_gemm_kernel<<<edgeBlocks, 256, SM_TOT>>>(pehi,  pelo,  pwh + 3*16384, pwl + 3*16384, U_b,  pe2);
    mma_gemm_kernel<<<edgeBlocks, 256, SM_TOT>>>(pehi,  pelo,  pwh + 4*16384, pwl + 4*16384, iU_b, pe3);
    mma_gemm_kernel<<<nodeBlocks, 256, SM_TOT>>>(pxnhi, pxnlo, pwh + 5*16384, pwl + 5*16384, Vf_b, pVxf);
    mma_gemm_kernel<<<nodeBlocks, 256, SM_TOT>>>(pxnhi, pxnlo, pwh + 6*16384, pwl + 6*16384, Vt_b, pVxt);
    etmp_kernel<<<Bb*Nn, Hh>>>(pe2, pe3, pVxf, pVxt, W_ph, eidx, inv_idx, pe1);
    rowstats_kernel<<<STATS_BLOCKS, Hh>>>(pe1, EDGE_ROWS);
    finalize_stats_kernel<<<1, Hh>>>(1.0f / (float)EDGE_ROWS);
    bn_apply_kernel<<<2048, 256>>>(e, pe1, bne_g, bne_b, enew, EDGE_ROWS);
}

// round 4
// speedup vs baseline: 3.5080x; 1.9848x over previous
#include <cuda_runtime.h>
#include <cuda_bf16.h>
#include <cstdint>

// ---------------- problem constants ----------------
#define Hh   128
#define Bb   16
#define Nn   1000
#define SFf  20
#define Ee   20000
#define NODE_ROWS (Bb*Nn)        // 16000  = 125*128
#define EDGE_ROWS (Bb*Ee)        // 320000 = 2500*128
#define BN_EPS 1e-5f
#define STATS_BLOCKS 256

// smem tile geometry: 128 x 136 bf16 per buffer (pad 8 -> conflict-free ldmatrix)
#define TPAD 136
#define TBUF (128*TPAD)          // elements per buffer

// ---------------- scratch (__device__ globals) ----------------
__device__ float g_Ux [NODE_ROWS*Hh];
__device__ float g_Vx [NODE_ROWS*Hh];
__device__ float g_Vxf[NODE_ROWS*Hh];
__device__ float g_Vxt[NODE_ROWS*Hh];
__device__ float g_e1 [(size_t)EDGE_ROWS*Hh];
__device__ float g_e2 [(size_t)EDGE_ROWS*Hh];
__device__ float g_e3 [(size_t)EDGE_ROWS*Hh];
__device__ float g_psum[STATS_BLOCKS*Hh];
__device__ float g_psq [STATS_BLOCKS*Hh];
__device__ float g_mean[Hh];
__device__ float g_rstd[Hh];
__device__ float g_pps[(size_t)(Bb*Nn)*Hh];   // per-(b,n) partial sums (edge BN)
__device__ float g_ppq[(size_t)(Bb*Nn)*Hh];

__device__ __nv_bfloat16 g_wthi[7][128*128];  // transposed [n][k] hi
__device__ __nv_bfloat16 g_wtlo[7][128*128];  // transposed [n][k] lo

// ---------------- helpers ----------------
__device__ __forceinline__ uint32_t smem_u32(const void* p) {
    uint32_t a;
    asm("{ .reg .u64 t; cvta.to.shared.u64 t, %1; cvt.u32.u64 %0, t; }" : "=r"(a) : "l"(p));
    return a;
}
__device__ __forceinline__ void ldsm_x4(uint32_t* r, uint32_t addr) {
    asm volatile("ldmatrix.sync.aligned.m8n8.x4.shared.b16 {%0,%1,%2,%3}, [%4];"
                 : "=r"(r[0]), "=r"(r[1]), "=r"(r[2]), "=r"(r[3]) : "r"(addr));
}
__device__ __forceinline__ void mma_bf16(float* c, const uint32_t* a, const uint32_t* b) {
    asm volatile("mma.sync.aligned.m16n8k16.row.col.f32.bf16.bf16.f32 "
                 "{%0,%1,%2,%3}, {%4,%5,%6,%7}, {%8,%9}, {%0,%1,%2,%3};"
                 : "+f"(c[0]), "+f"(c[1]), "+f"(c[2]), "+f"(c[3])
                 : "r"(a[0]), "r"(a[1]), "r"(a[2]), "r"(a[3]), "r"(b[0]), "r"(b[1]));
}

// ---------------- tensor-core GEMM (NW weight matrices sharing A) ----------------
// out_w[tile rows][128] = A[tile][128] @ W_w^T + bias_w   (W stored [n][k], bf16 hi/lo)
// A is fp32 in gmem; converted to bf16 hi/lo during smem fill.
// Split precision: D = Ah*Wh + Al*Wh + Ah*Wl (fp32 accum).
template<int NW>
__global__ __launch_bounds__(512)
void mma_gemm_kernel(const float* __restrict__ A,
                     const __nv_bfloat16* __restrict__ B0h, const __nv_bfloat16* __restrict__ B0l,
                     const float* __restrict__ bias0, float* __restrict__ out0,
                     const __nv_bfloat16* __restrict__ B1h, const __nv_bfloat16* __restrict__ B1l,
                     const float* __restrict__ bias1, float* __restrict__ out1)
{
    extern __shared__ __nv_bfloat16 sm[];
    __nv_bfloat16* Ash = sm;
    __nv_bfloat16* Als = sm + TBUF;
    __nv_bfloat16* Bh0 = sm + 2*TBUF;
    __nv_bfloat16* Bl0 = sm + 3*TBUF;
    __nv_bfloat16* Bh1 = sm + 4*TBUF;   // used only if NW==2
    __nv_bfloat16* Bl1 = sm + 5*TBUF;

    const int tid = threadIdx.x;
    const size_t row0 = (size_t)blockIdx.x * 128;

    // ---- A tile: 128x128 fp32 -> bf16 hi/lo (4096 float4, 512 threads, 8 iters) ----
    {
        const float4* gA = (const float4*)(A + row0*128);
        #pragma unroll
        for (int i = 0; i < 8; ++i) {
            int idx = i*512 + tid;            // 0..4095
            int r = idx >> 5, c = idx & 31;   // row, float4 chunk
            float4 v = gA[idx];
            float vv[4] = {v.x, v.y, v.z, v.w};
            __align__(8) __nv_bfloat16 h[4], l[4];
            #pragma unroll
            for (int j = 0; j < 4; ++j) {
                h[j] = __float2bfloat16(vv[j]);
                l[j] = __float2bfloat16(vv[j] - __bfloat162float(h[j]));
            }
            int o = r*TPAD + c*4;
            *(uint2*)(Ash + o) = *(const uint2*)h;
            *(uint2*)(Als + o) = *(const uint2*)l;
        }
    }
    // ---- B tiles: bf16, 2048 uint4 per buffer, 4 iters each ----
    {
        const uint4* b0h = (const uint4*)B0h;
        const uint4* b0l = (const uint4*)B0l;
        #pragma unroll
        for (int i = 0; i < 4; ++i) {
            int idx = i*512 + tid;            // 0..2047
            int r = idx >> 4, c = idx & 15;
            int o = r*TPAD + c*8;
            *(uint4*)(Bh0 + o) = b0h[idx];
            *(uint4*)(Bl0 + o) = b0l[idx];
        }
        if (NW == 2) {
            const uint4* b1h = (const uint4*)B1h;
            const uint4* b1l = (const uint4*)B1l;
            #pragma unroll
            for (int i = 0; i < 4; ++i) {
                int idx = i*512 + tid;
                int r = idx >> 4, c = idx & 15;
                int o = r*TPAD + c*8;
                *(uint4*)(Bh1 + o) = b1h[idx];
                *(uint4*)(Bl1 + o) = b1l[idx];
            }
        }
    }
    __syncthreads();

    const int warp = tid >> 5, lane = tid & 31;
    const int wr = warp >> 2;         // rows wr*32..+32
    const int wc = warp & 3;          // cols wc*32..+32

    float acc[NW][2][4][4];
    #pragma unroll
    for (int w = 0; w < NW; ++w)
        #pragma unroll
        for (int mt = 0; mt < 2; ++mt)
            #pragma unroll
            for (int nt = 0; nt < 4; ++nt)
                #pragma unroll
                for (int i = 0; i < 4; ++i) acc[w][mt][nt][i] = 0.f;

    const uint32_t a_hi = smem_u32(Ash), a_lo = smem_u32(Als);
    uint32_t b_hi[2], b_lo[2];
    b_hi[0] = smem_u32(Bh0); b_lo[0] = smem_u32(Bl0);
    b_hi[1] = smem_u32(Bh1); b_lo[1] = smem_u32(Bl1);

    const int a_row  = wr*32 + (lane & 15);
    const int a_koff = (lane >> 4) * 8;
    const int b_n    = wc*32 + (lane & 7) + ((lane >> 4) & 1)*8;
    const int b_koff = ((lane >> 3) & 1) * 8;

    #pragma unroll
    for (int ks = 0; ks < 8; ++ks) {
        const int k0 = ks * 16;
        uint32_t ah[2][4], al[2][4];
        #pragma unroll
        for (int mt = 0; mt < 2; ++mt) {
            uint32_t off = (uint32_t)((a_row + mt*16)*TPAD + k0 + a_koff) * 2u;
            ldsm_x4(ah[mt], a_hi + off);
            ldsm_x4(al[mt], a_lo + off);
        }
        #pragma unroll
        for (int w = 0; w < NW; ++w) {
            #pragma unroll
            for (int p = 0; p < 2; ++p) {
                uint32_t bh[4], bl[4];
                uint32_t off = (uint32_t)((b_n + p*16)*TPAD + k0 + b_koff) * 2u;
                ldsm_x4(bh, b_hi[w] + off);
                ldsm_x4(bl, b_lo[w] + off);
                #pragma unroll
                for (int mt = 0; mt < 2; ++mt) {
                    mma_bf16(acc[w][mt][2*p  ], ah[mt], bh);
                    mma_bf16(acc[w][mt][2*p  ], al[mt], bh);
                    mma_bf16(acc[w][mt][2*p  ], ah[mt], bl);
                    mma_bf16(acc[w][mt][2*p+1], ah[mt], bh + 2);
                    mma_bf16(acc[w][mt][2*p+1], al[mt], bh + 2);
                    mma_bf16(acc[w][mt][2*p+1], ah[mt], bl + 2);
                }
            }
        }
    }

    // ---- epilogue ----
    const int gid = lane >> 2, tg = lane & 3;
    #pragma unroll
    for (int w = 0; w < NW; ++w) {
        const float* bias = (w == 0) ? bias0 : bias1;
        float* out = (w == 0) ? out0 : out1;
        #pragma unroll
        for (int mt = 0; mt < 2; ++mt) {
            #pragma unroll
            for (int nt = 0; nt < 4; ++nt) {
                int col = wc*32 + nt*8 + tg*2;
                float b0 = bias[col], b1 = bias[col+1];
                size_t r0 = row0 + wr*32 + mt*16 + gid;
                *(float2*)(out + r0*128 + col) =
                    make_float2(acc[w][mt][nt][0] + b0, acc[w][mt][nt][1] + b1);
                *(float2*)(out + (r0+8)*128 + col) =
                    make_float2(acc[w][mt][nt][2] + b0, acc[w][mt][nt][3] + b1);
            }
        }
    }
}

// ---------------- all weights: transpose + hi/lo split (one launch) ----------------
struct WPtrs { const float* w[7]; };
__global__ __launch_bounds__(128)
void wsplit_all_kernel(WPtrs wp, __nv_bfloat16* __restrict__ hi, __nv_bfloat16* __restrict__ lo)
{
    int wi = blockIdx.y, k = blockIdx.x, c = threadIdx.x;
    float v = wp.w[wi][k*128 + c];
    __nv_bfloat16 h = __float2bfloat16(v);
    size_t o = (size_t)wi*16384 + c*128 + k;
    hi[o] = h;
    lo[o] = __float2bfloat16(v - __bfloat162float(h));
}

// ---------------- softmax over SF + gather-aggregate + Ux add ----------------
__global__ __launch_bounds__(Hh)
void softmax_agg_kernel(const float* __restrict__ Ve, const float* __restrict__ Vx,
                        const float* __restrict__ Ux_in, const int* __restrict__ edge_index,
                        float* __restrict__ xtmp)
{
    int bn = blockIdx.x;
    int b = bn / Nn, n = bn % Nn;
    int h = threadIdx.x;
    __shared__ int sidx[SFf];
    if (h < SFf) sidx[h] = edge_index[(size_t)b*Ee + n*SFf + h];
    __syncthreads();

    const float* vep = Ve + ((size_t)b*Ee + (size_t)n*SFf)*Hh + h;
    float v[SFf];
    float m = -1e30f;
    #pragma unroll
    for (int s = 0; s < SFf; ++s) { v[s] = vep[s*Hh]; m = fmaxf(m, v[s]); }
    float den = 0.f;
    #pragma unroll
    for (int s = 0; s < SFf; ++s) { v[s] = expf(v[s] - m); den += v[s]; }
    float agg = 0.f;
    #pragma unroll
    for (int s = 0; s < SFf; ++s)
        agg += v[s] * Vx[((size_t)b*Nn + sidx[s])*Hh + h];

    size_t o = (size_t)bn*Hh + h;
    xtmp[o] = Ux_in[o] + agg / den;
}

// ---------------- BN stats over a dense tensor ----------------
__global__ __launch_bounds__(Hh)
void rowstats_kernel(const float* __restrict__ t, int R)
{
    int h = threadIdx.x;
    float s = 0.f, q = 0.f;
    for (int r = blockIdx.x; r < R; r += gridDim.x) {
        float v = t[(size_t)r*Hh + h];
        s += v; q += v*v;
    }
    g_psum[blockIdx.x*Hh + h] = s;
    g_psq [blockIdx.x*Hh + h] = q;
}

// ---------------- reduce per-(b,n) partials -> 256 partials ----------------
__global__ __launch_bounds__(Hh)
void reduce_partials_kernel(const float* __restrict__ ps, const float* __restrict__ pq, int rows)
{
    int h = threadIdx.x;
    float s = 0.f, q = 0.f;
    for (int r = blockIdx.x; r < rows; r += gridDim.x) {
        s += ps[(size_t)r*Hh + h];
        q += pq[(size_t)r*Hh + h];
    }
    g_psum[blockIdx.x*Hh + h] = s;
    g_psq [blockIdx.x*Hh + h] = q;
}

// ---------------- finalize mean / rstd ----------------
__global__ __launch_bounds__(Hh)
void finalize_stats_kernel(float inv_count)
{
    int h = threadIdx.x;
    float s = 0.f, q = 0.f;
    #pragma unroll 8
    for (int i = 0; i < STATS_BLOCKS; ++i) { s += g_psum[i*Hh + h]; q += g_psq[i*Hh + h]; }
    float mean = s * inv_count;
    float var  = q * inv_count - mean*mean;
    g_mean[h] = mean;
    g_rstd[h] = rsqrtf(var + BN_EPS);
}

// ---------------- BN apply + ReLU + residual (float4) ----------------
__global__ __launch_bounds__(256)
void bn_apply_kernel(const float* __restrict__ resid, const float* __restrict__ tmp,
                     const float* __restrict__ gamma, const float* __restrict__ beta,
                     float* __restrict__ out, int R)
{
    size_t total = (size_t)R * 32;     // float4 groups
    for (size_t idx = (size_t)blockIdx.x*blockDim.x + threadIdx.x; idx < total;
         idx += (size_t)gridDim.x*blockDim.x) {
        int h4 = (int)(idx & 31) * 4;
        float4 t = ((const float4*)tmp)[idx];
        float4 r = ((const float4*)resid)[idx];
        float4 o;
        o.x = r.x + fmaxf((t.x - g_mean[h4  ]) * g_rstd[h4  ] * gamma[h4  ] + beta[h4  ], 0.f);
        o.y = r.y + fmaxf((t.y - g_mean[h4+1]) * g_rstd[h4+1] * gamma[h4+1] + beta[h4+1], 0.f);
        o.z = r.z + fmaxf((t.z - g_mean[h4+2]) * g_rstd[h4+2] * gamma[h4+2] + beta[h4+2], 0.f);
        o.w = r.w + fmaxf((t.w - g_mean[h4+3]) * g_rstd[h4+3] * gamma[h4+3] + beta[h4+3], 0.f);
        ((float4*)out)[idx] = o;
    }
}

// ---------------- e_tmp = Ue + Vxt[gather] + Vxf + inv_emb; emits BN partials ----------------
__global__ __launch_bounds__(Hh)
void etmp_kernel(const float* __restrict__ Ue,  const float* __restrict__ iUe,
                 const float* __restrict__ Vxf, const float* __restrict__ Vxt,
                 const float* __restrict__ Wph, const int* __restrict__ edge_index,
                 const int* __restrict__ inv_index, float* __restrict__ etmp,
                 float* __restrict__ pps, float* __restrict__ ppq)
{
    int bn = blockIdx.x;
    int b = bn / Nn, n = bn % Nn;
    int h = threadIdx.x;
    __shared__ int sidx[SFf], sinv[SFf];
    if (h < SFf) {
        sidx[h] = edge_index[(size_t)b*Ee + n*SFf + h];
        sinv[h] = inv_index [(size_t)b*Ee + n*SFf + h];
    }
    __syncthreads();

    float vf  = Vxf[((size_t)b*Nn + n)*Hh + h];
    float wph = Wph[h];
    float ssum = 0.f, ssq = 0.f;
    #pragma unroll
    for (int s = 0; s < SFf; ++s) {
        size_t eo = ((size_t)b*Ee + (size_t)n*SFf + s)*Hh + h;
        int inv = sinv[s];
        float ie = (inv < Ee) ? iUe[((size_t)b*Ee + inv)*Hh + h] : wph;
        float val = Ue[eo] + Vxt[((size_t)b*Nn + sidx[s])*Hh + h] + vf + ie;
        etmp[eo] = val;
        ssum += val; ssq += val*val;
    }
    pps[(size_t)bn*Hh + h] = ssum;
    ppq[(size_t)bn*Hh + h] = ssq;
}

// ---------------- launch ----------------
extern "C" void kernel_launch(void* const* d_in, const int* in_sizes, int n_in,
                              void* d_out, int out_size)
{
    const float* x       = (const float*)d_in[0];
    const float* e       = (const float*)d_in[1];
    const int*   eidx    = (const int*)  d_in[2];
    const int*   inv_idx = (const int*)  d_in[3];
    const float* node_w  = (const float*)d_in[4];
    const float* node_b  = (const float*)d_in[5];
    const float* to_w    = (const float*)d_in[6];
    const float* to_b    = (const float*)d_in[7];
    const float* ee_w    = (const float*)d_in[8];
    const float* ee_b    = (const float*)d_in[9];
    const float* U_w     = (const float*)d_in[10];
    const float* U_b     = (const float*)d_in[11];
    const float* Vf_w    = (const float*)d_in[12];
    const float* Vf_b    = (const float*)d_in[13];
    const float* Vt_w    = (const float*)d_in[14];
    const float* Vt_b    = (const float*)d_in[15];
    const float* iU_w    = (const float*)d_in[16];
    const float* iU_b    = (const float*)d_in[17];
    const float* W_ph    = (const float*)d_in[18];
    const float* bnn_g   = (const float*)d_in[19];
    const float* bnn_b   = (const float*)d_in[20];
    const float* bne_g   = (const float*)d_in[21];
    const float* bne_b   = (const float*)d_in[22];

    float* out  = (float*)d_out;
    float* xnew = out;
    float* enew = out + (size_t)NODE_ROWS*Hh;

    float *pUx, *pVx, *pVxf, *pVxt, *pe1, *pe2, *pe3, *pps, *ppq;
    cudaGetSymbolAddress((void**)&pUx,  g_Ux);
    cudaGetSymbolAddress((void**)&pVx,  g_Vx);
    cudaGetSymbolAddress((void**)&pVxf, g_Vxf);
    cudaGetSymbolAddress((void**)&pVxt, g_Vxt);
    cudaGetSymbolAddress((void**)&pe1,  g_e1);
    cudaGetSymbolAddress((void**)&pe2,  g_e2);
    cudaGetSymbolAddress((void**)&pe3,  g_e3);
    cudaGetSymbolAddress((void**)&pps,  g_pps);
    cudaGetSymbolAddress((void**)&ppq,  g_ppq);

    __nv_bfloat16 *pwh, *pwl;
    cudaGetSymbolAddress((void**)&pwh, g_wthi);
    cudaGetSymbolAddress((void**)&pwl, g_wtlo);

    const int SM1 = 4*TBUF*2;   // NW=1: 139264 B
    const int SM2 = 6*TBUF*2;   // NW=2: 208896 B
    cudaFuncSetAttribute(mma_gemm_kernel<1>, cudaFuncAttributeMaxDynamicSharedMemorySize, SM1);
    cudaFuncSetAttribute(mma_gemm_kernel<2>, cudaFuncAttributeMaxDynamicSharedMemorySize, SM2);

    const int nodeBlocks = NODE_ROWS / 128;   // 125
    const int edgeBlocks = EDGE_ROWS / 128;   // 2500

    // weight order: 0=node,1=to,2=ee,3=U,4=iU,5=Vf,6=Vt
    WPtrs wp; wp.w[0]=node_w; wp.w[1]=to_w; wp.w[2]=ee_w; wp.w[3]=U_w; wp.w[4]=iU_w; wp.w[5]=Vf_w; wp.w[6]=Vt_w;
    wsplit_all_kernel<<<dim3(128,7), 128>>>(wp, pwh, pwl);

    // ---- NodeFeatures ----
    mma_gemm_kernel<2><<<nodeBlocks, 512, SM2>>>(x,
        pwh + 0*16384, pwl + 0*16384, node_b, pUx,
        pwh + 1*16384, pwl + 1*16384, to_b,   pVx);
    mma_gemm_kernel<1><<<edgeBlocks, 512, SM1>>>(e,
        pwh + 2*16384, pwl + 2*16384, ee_b, pe1,
        (const __nv_bfloat16*)nullptr, (const __nv_bfloat16*)nullptr, (const float*)nullptr, (float*)nullptr);
    // U/iU GEMM only depends on e — overlaps node elementwise chain in-order is fine
    mma_gemm_kernel<2><<<edgeBlocks, 512, SM2>>>(e,
        pwh + 3*16384, pwl + 3*16384, U_b,  pe2,
        pwh + 4*16384, pwl + 4*16384, iU_b, pe3);

    softmax_agg_kernel<<<Bb*Nn, Hh>>>(pe1, pVx, pUx, eidx, pUx);
    rowstats_kernel<<<STATS_BLOCKS, Hh>>>(pUx, NODE_ROWS);
    finalize_stats_kernel<<<1, Hh>>>(1.0f / (float)NODE_ROWS);
    bn_apply_kernel<<<1024, 256>>>(x, pUx, bnn_g, bnn_b, xnew, NODE_ROWS);

    // ---- EdgeFeatures ----
    mma_gemm_kernel<2><<<nodeBlocks, 512, SM2>>>(xnew,
        pwh + 5*16384, pwl + 5*16384, Vf_b, pVxf,
        pwh + 6*16384, pwl + 6*16384, Vt_b, pVxt);
    etmp_kernel<<<Bb*Nn, Hh>>>(pe2, pe3, pVxf, pVxt, W_ph, eidx, inv_idx, pe1, pps, ppq);
    reduce_partials_kernel<<<STATS_BLOCKS, Hh>>>(pps, ppq, Bb*Nn);
    finalize_stats_kernel<<<1, Hh>>>(1.0f / (float)EDGE_ROWS);
    bn_apply_kernel<<<4096, 256>>>(e, pe1, bne_g, bne_b, enew, EDGE_ROWS);
}